// round 3
// baseline (speedup 1.0000x reference)
#include <cuda_runtime.h>
#include <cuda_bf16.h>
#include <mma.h>

using namespace nvcuda;

#define NN 50000
#define NNP 50048              // 391 * 128, padded for unguarded wmma stores
#define NE 800000
#define FD 256

// ---------------- device scratch (no allocations allowed) ----------------
__device__ float g_dis[NN];        // degree, then deg^-1/2 in place
__device__ int   g_cnt[NN];        // edge count per row
__device__ int   g_off[NN];        // CSR row offsets (exclusive scan of cnt)
__device__ int   g_cur[NN];        // scatter cursors
__device__ int   g_col[NE];        // CSR col indices
__device__ float g_w[NE];          // CSR normalized weights
__device__ float g_y[(size_t)NNP * FD]; // y = x @ W^T (padded rows)
__device__ int   g_is64;           // edge_index dtype flag

__device__ __forceinline__ int edge_at(const void* ei, long long idx) {
    if (g_is64) return (int)((const long long*)ei)[idx];
    return ((const int*)ei)[idx];
}

// ---------------- init + dtype detect (block 0) ----------------
__global__ void k_init(const int* __restrict__ ei32) {
    int i = blockIdx.x * blockDim.x + threadIdx.x;
    if (i < NN) { g_dis[i] = 0.0f; g_cnt[i] = 0; }
    if (blockIdx.x == 0) {
        // int64 indices < 50000 => every odd 32-bit word is zero
        int nz = 0;
        if (threadIdx.x < 128) nz = (ei32[2 * threadIdx.x + 1] != 0) ? 1 : 0;
        int any = __syncthreads_or(nz);
        if (threadIdx.x == 0) g_is64 = (any == 0) ? 1 : 0;
    }
}

// ---------------- degree accumulation ----------------
__global__ void k_deg(const void* __restrict__ ei, const float* __restrict__ C) {
    int e = blockIdx.x * blockDim.x + threadIdx.x;
    if (e < NE) {
        int r = edge_at(ei, e);
        atomicAdd(&g_dis[r], C[e]);
        atomicAdd(&g_cnt[r], 1);
    }
}

// ---------------- deg^-1/2 + single-block exclusive scan ----------------
__global__ void k_scan() {
    __shared__ int s[1024];
    const int t = threadIdx.x;
    const int CH = (NN + 1023) / 1024; // 49
    const int base = t * CH;

    // deg^-1/2 in place (merged from k_dis)
    for (int i = 0; i < CH; i++) {
        int idx = base + i;
        if (idx < NN) {
            float d = g_dis[idx];
            g_dis[idx] = (d > 0.0f) ? rsqrtf(d) : 0.0f;
        }
    }

    int sum = 0;
    for (int i = 0; i < CH; i++) {
        int idx = base + i;
        if (idx < NN) sum += g_cnt[idx];
    }
    s[t] = sum;
    __syncthreads();
    for (int off = 1; off < 1024; off <<= 1) {
        int v = (t >= off) ? s[t - off] : 0;
        __syncthreads();
        s[t] += v;
        __syncthreads();
    }
    int run = (t == 0) ? 0 : s[t - 1];
    for (int i = 0; i < CH; i++) {
        int idx = base + i;
        if (idx < NN) {
            g_off[idx] = run;
            g_cur[idx] = run;
            run += g_cnt[idx];
        }
    }
}

// ---------------- scatter edges into CSR + compute normalized weights ----
__global__ void k_scatter(const void* __restrict__ ei, const float* __restrict__ C) {
    int e = blockIdx.x * blockDim.x + threadIdx.x;
    if (e < NE) {
        int r  = edge_at(ei, e);
        int cl = edge_at(ei, (long long)NE + e);
        float w = g_dis[r] * C[e] * g_dis[cl];
        int p = atomicAdd(&g_cur[r], 1);
        g_col[p] = cl;
        g_w[p]   = w;
    }
}

// ---------------- tf32 tensor-core GEMM: y[M,256] = x[M,256] @ W^T ------
// Block tile 128x128, 8 warps (2x4), warp tile 64x32 (4x2 wmma m16n16k8).
// BK=16, double-buffered smem, one __syncthreads per chunk.
#define GM_BM 128
#define GM_BN 128
#define GM_BK 16
#define BKP   20   // padded ld (floats); 80B, multiple of 16B

__global__ __launch_bounds__(256) void k_gemm_tc(const float* __restrict__ A,
                                                 const float* __restrict__ B) {
    __shared__ __align__(16) float As[2][GM_BM][BKP];
    __shared__ __align__(16) float Bs[2][GM_BN][BKP];

    const int tid = threadIdx.x;
    const int w  = tid >> 5;
    const int wm = w >> 2;     // 0..1 -> 64-row slab
    const int wn = w & 3;      // 0..3 -> 32-col slab
    const int bm = blockIdx.x, bn = blockIdx.y;

    wmma::fragment<wmma::accumulator, 16, 16, 8, float> acc[4][2];
#pragma unroll
    for (int i = 0; i < 4; i++)
#pragma unroll
        for (int j = 0; j < 2; j++) wmma::fill_fragment(acc[i][j], 0.0f);

    // per chunk: A tile 128x16 = 512 float4 -> 2/thread; B same
    int aR[2], aC[2];
#pragma unroll
    for (int i = 0; i < 2; i++) {
        int f = tid + 256 * i;
        aR[i] = f >> 2;          // 0..127
        aC[i] = (f & 3) * 4;     // 0,4,8,12
    }
    int gAr[2]; bool av[2]; int gBr[2];
#pragma unroll
    for (int i = 0; i < 2; i++) {
        gAr[i] = bm * GM_BM + aR[i];
        av[i]  = (gAr[i] < NN);
        gBr[i] = bn * GM_BN + aR[i];   // rows 0..255, always valid
    }

    const float4 z4 = make_float4(0.f, 0.f, 0.f, 0.f);
    float4 ra[2], rb[2];

    // prologue: chunk 0 -> buffer 0
#pragma unroll
    for (int i = 0; i < 2; i++) {
        ra[i] = av[i] ? *(const float4*)(A + (size_t)gAr[i] * FD + aC[i]) : z4;
        rb[i] = *(const float4*)(B + (size_t)gBr[i] * FD + aC[i]);
    }
#pragma unroll
    for (int i = 0; i < 2; i++) {
        *(float4*)&As[0][aR[i]][aC[i]] = ra[i];
        *(float4*)&Bs[0][aR[i]][aC[i]] = rb[i];
    }
    __syncthreads();

    const int NCH = FD / GM_BK; // 16
    for (int c = 0; c < NCH; c++) {
        const int p = c & 1, q = p ^ 1;
        if (c < NCH - 1) {
            const int k0 = (c + 1) * GM_BK;
#pragma unroll
            for (int i = 0; i < 2; i++) {
                ra[i] = av[i] ? *(const float4*)(A + (size_t)gAr[i] * FD + k0 + aC[i]) : z4;
                rb[i] = *(const float4*)(B + (size_t)gBr[i] * FD + k0 + aC[i]);
            }
        }

#pragma unroll
        for (int ks = 0; ks < 2; ks++) {
            const int k0 = ks * 8;
            wmma::fragment<wmma::matrix_a, 16, 16, 8, wmma::precision::tf32, wmma::row_major> af[4];
            wmma::fragment<wmma::matrix_b, 16, 16, 8, wmma::precision::tf32, wmma::col_major> bf[2];
#pragma unroll
            for (int i = 0; i < 4; i++)
                wmma::load_matrix_sync(af[i], &As[p][wm * 64 + i * 16][k0], BKP);
#pragma unroll
            for (int j = 0; j < 2; j++)
                wmma::load_matrix_sync(bf[j], &Bs[p][wn * 32 + j * 16][k0], BKP);
#pragma unroll
            for (int i = 0; i < 4; i++)
#pragma unroll
                for (int t = 0; t < af[i].num_elements; t++)
                    af[i].x[t] = wmma::__float_to_tf32(af[i].x[t]);
#pragma unroll
            for (int j = 0; j < 2; j++)
#pragma unroll
                for (int t = 0; t < bf[j].num_elements; t++)
                    bf[j].x[t] = wmma::__float_to_tf32(bf[j].x[t]);
#pragma unroll
            for (int i = 0; i < 4; i++)
#pragma unroll
                for (int j = 0; j < 2; j++)
                    wmma::mma_sync(acc[i][j], af[i], bf[j], acc[i][j]);
        }

        if (c < NCH - 1) {
#pragma unroll
            for (int i = 0; i < 2; i++) {
                *(float4*)&As[q][aR[i]][aC[i]] = ra[i];
                *(float4*)&Bs[q][aR[i]][aC[i]] = rb[i];
            }
            __syncthreads();
        }
    }

    // epilogue: unguarded stores into padded g_y (NNP rows)
#pragma unroll
    for (int i = 0; i < 4; i++) {
        int gr = bm * GM_BM + wm * 64 + i * 16;
#pragma unroll
        for (int j = 0; j < 2; j++) {
            int gc = bn * GM_BN + wn * 32 + j * 16;
            wmma::store_matrix_sync(g_y + (size_t)gr * FD + gc, acc[i][j], FD,
                                    wmma::mem_row_major);
        }
    }
}

// ---------------- SpMM: out[i] = b + sum_e w[e] * y[col[e]]  (warp per row)
__device__ __forceinline__ void fma_row(float4& a0, float4& a1, float w,
                                        const float4* yr, int lane) {
    float4 u0 = yr[lane * 2], u1 = yr[lane * 2 + 1];
    a0.x = fmaf(w, u0.x, a0.x); a0.y = fmaf(w, u0.y, a0.y);
    a0.z = fmaf(w, u0.z, a0.z); a0.w = fmaf(w, u0.w, a0.w);
    a1.x = fmaf(w, u1.x, a1.x); a1.y = fmaf(w, u1.y, a1.y);
    a1.z = fmaf(w, u1.z, a1.z); a1.w = fmaf(w, u1.w, a1.w);
}

__global__ __launch_bounds__(256) void k_spmm(const float* __restrict__ bias,
                                              float* __restrict__ out) {
    int gwarp = (blockIdx.x * blockDim.x + threadIdx.x) >> 5;
    int lane  = threadIdx.x & 31;
    if (gwarp >= NN) return;

    const int beg = g_off[gwarp];
    const int end = beg + g_cnt[gwarp];

    const float4* b4 = (const float4*)bias;
    float4 acc0 = b4[lane * 2];
    float4 acc1 = b4[lane * 2 + 1];

    int p = beg;
    for (; p + 3 < end; p += 4) {
        int   c0 = g_col[p],     c1 = g_col[p + 1];
        int   c2 = g_col[p + 2], c3 = g_col[p + 3];
        float w0 = g_w[p],       w1 = g_w[p + 1];
        float w2 = g_w[p + 2],   w3 = g_w[p + 3];
        const float4* y0 = (const float4*)(g_y + (size_t)c0 * FD);
        const float4* y1 = (const float4*)(g_y + (size_t)c1 * FD);
        const float4* y2 = (const float4*)(g_y + (size_t)c2 * FD);
        const float4* y3 = (const float4*)(g_y + (size_t)c3 * FD);
        float4 u0 = y0[lane * 2], u1 = y0[lane * 2 + 1];
        float4 v0 = y1[lane * 2], v1 = y1[lane * 2 + 1];
        float4 s0 = y2[lane * 2], s1 = y2[lane * 2 + 1];
        float4 t0 = y3[lane * 2], t1 = y3[lane * 2 + 1];
        acc0.x = fmaf(w0, u0.x, acc0.x); acc0.y = fmaf(w0, u0.y, acc0.y);
        acc0.z = fmaf(w0, u0.z, acc0.z); acc0.w = fmaf(w0, u0.w, acc0.w);
        acc1.x = fmaf(w0, u1.x, acc1.x); acc1.y = fmaf(w0, u1.y, acc1.y);
        acc1.z = fmaf(w0, u1.z, acc1.z); acc1.w = fmaf(w0, u1.w, acc1.w);
        acc0.x = fmaf(w1, v0.x, acc0.x); acc0.y = fmaf(w1, v0.y, acc0.y);
        acc0.z = fmaf(w1, v0.z, acc0.z); acc0.w = fmaf(w1, v0.w, acc0.w);
        acc1.x = fmaf(w1, v1.x, acc1.x); acc1.y = fmaf(w1, v1.y, acc1.y);
        acc1.z = fmaf(w1, v1.z, acc1.z); acc1.w = fmaf(w1, v1.w, acc1.w);
        acc0.x = fmaf(w2, s0.x, acc0.x); acc0.y = fmaf(w2, s0.y, acc0.y);
        acc0.z = fmaf(w2, s0.z, acc0.z); acc0.w = fmaf(w2, s0.w, acc0.w);
        acc1.x = fmaf(w2, s1.x, acc1.x); acc1.y = fmaf(w2, s1.y, acc1.y);
        acc1.z = fmaf(w2, s1.z, acc1.z); acc1.w = fmaf(w2, s1.w, acc1.w);
        acc0.x = fmaf(w3, t0.x, acc0.x); acc0.y = fmaf(w3, t0.y, acc0.y);
        acc0.z = fmaf(w3, t0.z, acc0.z); acc0.w = fmaf(w3, t0.w, acc0.w);
        acc1.x = fmaf(w3, t1.x, acc1.x); acc1.y = fmaf(w3, t1.y, acc1.y);
        acc1.z = fmaf(w3, t1.z, acc1.z); acc1.w = fmaf(w3, t1.w, acc1.w);
    }
    for (; p < end; p++) {
        fma_row(acc0, acc1, g_w[p], (const float4*)(g_y + (size_t)g_col[p] * FD), lane);
    }

    float4* o = (float4*)(out + (size_t)gwarp * FD);
    o[lane * 2]     = acc0;
    o[lane * 2 + 1] = acc1;
}

// ---------------- launch (GEMM forked onto a side stream) ----------------
extern "C" void kernel_launch(void* const* d_in, const int* in_sizes, int n_in,
                              void* d_out, int out_size) {
    const float* x  = (const float*)d_in[0];
    const void*  ei = d_in[1];                 // int32 or int64, detected on device
    const float* C  = (const float*)d_in[2];
    const float* W  = (const float*)d_in[3];
    const float* b  = (const float*)d_in[4];
    float* out = (float*)d_out;

    // Fresh fork stream + events each call (no static state; kernel_launch is
    // invoked only a handful of times by the harness, so the handle leak is
    // bounded and host-side only).
    cudaStream_t s2;
    cudaStreamCreateWithFlags(&s2, cudaStreamNonBlocking);
    cudaEvent_t eFork, eJoin;
    cudaEventCreateWithFlags(&eFork, cudaEventDisableTiming);
    cudaEventCreateWithFlags(&eJoin, cudaEventDisableTiming);

    // fork: GEMM (depends only on x, W) runs concurrently with CSR build
    cudaEventRecord(eFork, 0);
    cudaStreamWaitEvent(s2, eFork, 0);
    dim3 gg((NNP + GM_BM - 1) / GM_BM, FD / GM_BN);
    k_gemm_tc<<<gg, 256, 0, s2>>>(x, W);
    cudaEventRecord(eJoin, s2);

    // CSR build pipeline on the default stream
    k_init<<<(NN + 255) / 256, 256>>>((const int*)ei);
    k_deg<<<(NE + 255) / 256, 256>>>(ei, C);
    k_scan<<<1, 1024>>>();
    k_scatter<<<(NE + 255) / 256, 256>>>(ei, C);

    // join: SpMM needs both g_y and the CSR
    cudaStreamWaitEvent(0, eJoin, 0);
    k_spmm<<<(NN * 32 + 255) / 256, 256>>>(b, out);
}

// round 4
// speedup vs baseline: 1.6037x; 1.6037x over previous
#include <cuda_runtime.h>
#include <cuda_bf16.h>
#include <mma.h>

using namespace nvcuda;

#define NN 50000
#define NNP 50048              // 391 * 128, padded for unguarded wmma stores
#define NE 800000
#define FD 256
#define NB 196                 // (NN + 255) / 256 scan blocks

// ---------------- device scratch (no allocations allowed) ----------------
__device__ float g_dis[NN];        // degree, then deg^-1/2 in place
__device__ int   g_cnt[NN];        // edge count per row
__device__ int   g_off[NN];        // CSR row offsets (exclusive scan of cnt)
__device__ int   g_cur[NN];        // scatter cursors
__device__ int   g_col[NE];        // CSR col indices
__device__ float g_w[NE];          // CSR normalized weights
__device__ float g_y[(size_t)NNP * FD]; // y = x @ W^T (padded rows)
__device__ int   g_blk[NB];        // per-block count sums
__device__ int   g_blkoff[NB];     // exclusive scan of block sums
__device__ int   g_is64;           // edge_index dtype flag

__device__ __forceinline__ int edge_at(const void* ei, long long idx) {
    if (g_is64) return (int)((const long long*)ei)[idx];
    return ((const int*)ei)[idx];
}

// ---------------- init + dtype detect (block 0) ----------------
__global__ void k_init(const int* __restrict__ ei32) {
    int i = blockIdx.x * blockDim.x + threadIdx.x;
    if (i < NN) { g_dis[i] = 0.0f; g_cnt[i] = 0; }
    if (blockIdx.x == 0) {
        // int64 indices < 50000 => every odd 32-bit word is zero
        int nz = 0;
        if (threadIdx.x < 128) nz = (ei32[2 * threadIdx.x + 1] != 0) ? 1 : 0;
        int any = __syncthreads_or(nz);
        if (threadIdx.x == 0) g_is64 = (any == 0) ? 1 : 0;
    }
}

// ---------------- degree accumulation ----------------
__global__ void k_deg(const void* __restrict__ ei, const float* __restrict__ C) {
    int e = blockIdx.x * blockDim.x + threadIdx.x;
    if (e < NE) {
        int r = edge_at(ei, e);
        atomicAdd(&g_dis[r], C[e]);
        atomicAdd(&g_cnt[r], 1);
    }
}

// ---------------- hierarchical scan, stage 1: rsqrt + per-block sums ----
__global__ __launch_bounds__(256) void k_scan1() {
    __shared__ int s[256];
    int t = threadIdx.x;
    int i = blockIdx.x * 256 + t;
    int v = 0;
    if (i < NN) {
        float d = g_dis[i];
        g_dis[i] = (d > 0.0f) ? rsqrtf(d) : 0.0f;
        v = g_cnt[i];
    }
    s[t] = v;
    __syncthreads();
#pragma unroll
    for (int off = 128; off > 0; off >>= 1) {
        if (t < off) s[t] += s[t + off];
        __syncthreads();
    }
    if (t == 0) g_blk[blockIdx.x] = s[0];
}

// ---------------- stage 2: exclusive scan of NB block sums (1 block) -----
__global__ __launch_bounds__(256) void k_scan2() {
    __shared__ int s[256];
    int t = threadIdx.x;
    int v = (t < NB) ? g_blk[t] : 0;
    s[t] = v;
    __syncthreads();
#pragma unroll
    for (int off = 1; off < 256; off <<= 1) {
        int u = (t >= off) ? s[t - off] : 0;
        __syncthreads();
        s[t] += u;
        __syncthreads();
    }
    if (t < NB) g_blkoff[t] = s[t] - v;   // exclusive
}

// ---------------- stage 3: per-block exclusive scan + global offset ------
__global__ __launch_bounds__(256) void k_scan3() {
    __shared__ int s[256];
    int t = threadIdx.x;
    int i = blockIdx.x * 256 + t;
    int v = (i < NN) ? g_cnt[i] : 0;
    s[t] = v;
    __syncthreads();
#pragma unroll
    for (int off = 1; off < 256; off <<= 1) {
        int u = (t >= off) ? s[t - off] : 0;
        __syncthreads();
        s[t] += u;
        __syncthreads();
    }
    if (i < NN) {
        int excl = g_blkoff[blockIdx.x] + s[t] - v;
        g_off[i] = excl;
        g_cur[i] = excl;
    }
}

// ---------------- scatter edges into CSR + compute normalized weights ----
__global__ void k_scatter(const void* __restrict__ ei, const float* __restrict__ C) {
    int e = blockIdx.x * blockDim.x + threadIdx.x;
    if (e < NE) {
        int r  = edge_at(ei, e);
        int cl = edge_at(ei, (long long)NE + e);
        float w = g_dis[r] * C[e] * g_dis[cl];
        int p = atomicAdd(&g_cur[r], 1);
        g_col[p] = cl;
        g_w[p]   = w;
    }
}

// ---------------- tf32 tensor-core GEMM: y[M,256] = x[M,256] @ W^T ------
// Block tile 128x128, 8 warps (2x4), warp tile 64x32 (4x2 wmma m16n16k8).
// BK=16, double-buffered smem, one __syncthreads per chunk.
#define GM_BM 128
#define GM_BN 128
#define GM_BK 16
#define BKP   20   // padded ld (floats); 80B, multiple of 16B

__global__ __launch_bounds__(256) void k_gemm_tc(const float* __restrict__ A,
                                                 const float* __restrict__ B) {
    __shared__ __align__(16) float As[2][GM_BM][BKP];
    __shared__ __align__(16) float Bs[2][GM_BN][BKP];

    const int tid = threadIdx.x;
    const int w  = tid >> 5;
    const int wm = w >> 2;     // 0..1 -> 64-row slab
    const int wn = w & 3;      // 0..3 -> 32-col slab
    const int bm = blockIdx.x, bn = blockIdx.y;

    wmma::fragment<wmma::accumulator, 16, 16, 8, float> acc[4][2];
#pragma unroll
    for (int i = 0; i < 4; i++)
#pragma unroll
        for (int j = 0; j < 2; j++) wmma::fill_fragment(acc[i][j], 0.0f);

    int aR[2], aC[2];
#pragma unroll
    for (int i = 0; i < 2; i++) {
        int f = tid + 256 * i;
        aR[i] = f >> 2;          // 0..127
        aC[i] = (f & 3) * 4;     // 0,4,8,12
    }
    int gAr[2]; bool av[2]; int gBr[2];
#pragma unroll
    for (int i = 0; i < 2; i++) {
        gAr[i] = bm * GM_BM + aR[i];
        av[i]  = (gAr[i] < NN);
        gBr[i] = bn * GM_BN + aR[i];
    }

    const float4 z4 = make_float4(0.f, 0.f, 0.f, 0.f);
    float4 ra[2], rb[2];

#pragma unroll
    for (int i = 0; i < 2; i++) {
        ra[i] = av[i] ? *(const float4*)(A + (size_t)gAr[i] * FD + aC[i]) : z4;
        rb[i] = *(const float4*)(B + (size_t)gBr[i] * FD + aC[i]);
    }
#pragma unroll
    for (int i = 0; i < 2; i++) {
        *(float4*)&As[0][aR[i]][aC[i]] = ra[i];
        *(float4*)&Bs[0][aR[i]][aC[i]] = rb[i];
    }
    __syncthreads();

    const int NCH = FD / GM_BK; // 16
    for (int c = 0; c < NCH; c++) {
        const int p = c & 1, q = p ^ 1;
        if (c < NCH - 1) {
            const int k0 = (c + 1) * GM_BK;
#pragma unroll
            for (int i = 0; i < 2; i++) {
                ra[i] = av[i] ? *(const float4*)(A + (size_t)gAr[i] * FD + k0 + aC[i]) : z4;
                rb[i] = *(const float4*)(B + (size_t)gBr[i] * FD + k0 + aC[i]);
            }
        }

#pragma unroll
        for (int ks = 0; ks < 2; ks++) {
            const int k0 = ks * 8;
            wmma::fragment<wmma::matrix_a, 16, 16, 8, wmma::precision::tf32, wmma::row_major> af[4];
            wmma::fragment<wmma::matrix_b, 16, 16, 8, wmma::precision::tf32, wmma::col_major> bf[2];
#pragma unroll
            for (int i = 0; i < 4; i++)
                wmma::load_matrix_sync(af[i], &As[p][wm * 64 + i * 16][k0], BKP);
#pragma unroll
            for (int j = 0; j < 2; j++)
                wmma::load_matrix_sync(bf[j], &Bs[p][wn * 32 + j * 16][k0], BKP);
#pragma unroll
            for (int i = 0; i < 4; i++)
#pragma unroll
                for (int t = 0; t < af[i].num_elements; t++)
                    af[i].x[t] = wmma::__float_to_tf32(af[i].x[t]);
#pragma unroll
            for (int j = 0; j < 2; j++)
#pragma unroll
                for (int t = 0; t < bf[j].num_elements; t++)
                    bf[j].x[t] = wmma::__float_to_tf32(bf[j].x[t]);
#pragma unroll
            for (int i = 0; i < 4; i++)
#pragma unroll
                for (int j = 0; j < 2; j++)
                    wmma::mma_sync(acc[i][j], af[i], bf[j], acc[i][j]);
        }

        if (c < NCH - 1) {
#pragma unroll
            for (int i = 0; i < 2; i++) {
                *(float4*)&As[q][aR[i]][aC[i]] = ra[i];
                *(float4*)&Bs[q][aR[i]][aC[i]] = rb[i];
            }
            __syncthreads();
        }
    }

#pragma unroll
    for (int i = 0; i < 4; i++) {
        int gr = bm * GM_BM + wm * 64 + i * 16;
#pragma unroll
        for (int j = 0; j < 2; j++) {
            int gc = bn * GM_BN + wn * 32 + j * 16;
            wmma::store_matrix_sync(g_y + (size_t)gr * FD + gc, acc[i][j], FD,
                                    wmma::mem_row_major);
        }
    }
}

// ---------------- SpMM: out[i] = b + sum_e w[e] * y[col[e]]  (warp per row)
__device__ __forceinline__ void fma_row(float4& a0, float4& a1, float w,
                                        const float4* yr, int lane) {
    float4 u0 = yr[lane * 2], u1 = yr[lane * 2 + 1];
    a0.x = fmaf(w, u0.x, a0.x); a0.y = fmaf(w, u0.y, a0.y);
    a0.z = fmaf(w, u0.z, a0.z); a0.w = fmaf(w, u0.w, a0.w);
    a1.x = fmaf(w, u1.x, a1.x); a1.y = fmaf(w, u1.y, a1.y);
    a1.z = fmaf(w, u1.z, a1.z); a1.w = fmaf(w, u1.w, a1.w);
}

__global__ __launch_bounds__(256) void k_spmm(const float* __restrict__ bias,
                                              float* __restrict__ out) {
    int gwarp = (blockIdx.x * blockDim.x + threadIdx.x) >> 5;
    int lane  = threadIdx.x & 31;
    if (gwarp >= NN) return;

    const int beg = g_off[gwarp];
    const int end = beg + g_cnt[gwarp];

    const float4* b4 = (const float4*)bias;
    float4 acc0 = b4[lane * 2];
    float4 acc1 = b4[lane * 2 + 1];

    int p = beg;
    for (; p + 3 < end; p += 4) {
        int   c0 = g_col[p],     c1 = g_col[p + 1];
        int   c2 = g_col[p + 2], c3 = g_col[p + 3];
        float w0 = g_w[p],       w1 = g_w[p + 1];
        float w2 = g_w[p + 2],   w3 = g_w[p + 3];
        const float4* y0 = (const float4*)(g_y + (size_t)c0 * FD);
        const float4* y1 = (const float4*)(g_y + (size_t)c1 * FD);
        const float4* y2 = (const float4*)(g_y + (size_t)c2 * FD);
        const float4* y3 = (const float4*)(g_y + (size_t)c3 * FD);
        float4 u0 = y0[lane * 2], u1 = y0[lane * 2 + 1];
        float4 v0 = y1[lane * 2], v1 = y1[lane * 2 + 1];
        float4 s0 = y2[lane * 2], s1 = y2[lane * 2 + 1];
        float4 t0 = y3[lane * 2], t1 = y3[lane * 2 + 1];
        acc0.x = fmaf(w0, u0.x, acc0.x); acc0.y = fmaf(w0, u0.y, acc0.y);
        acc0.z = fmaf(w0, u0.z, acc0.z); acc0.w = fmaf(w0, u0.w, acc0.w);
        acc1.x = fmaf(w0, u1.x, acc1.x); acc1.y = fmaf(w0, u1.y, acc1.y);
        acc1.z = fmaf(w0, u1.z, acc1.z); acc1.w = fmaf(w0, u1.w, acc1.w);
        acc0.x = fmaf(w1, v0.x, acc0.x); acc0.y = fmaf(w1, v0.y, acc0.y);
        acc0.z = fmaf(w1, v0.z, acc0.z); acc0.w = fmaf(w1, v0.w, acc0.w);
        acc1.x = fmaf(w1, v1.x, acc1.x); acc1.y = fmaf(w1, v1.y, acc1.y);
        acc1.z = fmaf(w1, v1.z, acc1.z); acc1.w = fmaf(w1, v1.w, acc1.w);
        acc0.x = fmaf(w2, s0.x, acc0.x); acc0.y = fmaf(w2, s0.y, acc0.y);
        acc0.z = fmaf(w2, s0.z, acc0.z); acc0.w = fmaf(w2, s0.w, acc0.w);
        acc1.x = fmaf(w2, s1.x, acc1.x); acc1.y = fmaf(w2, s1.y, acc1.y);
        acc1.z = fmaf(w2, s1.z, acc1.z); acc1.w = fmaf(w2, s1.w, acc1.w);
        acc0.x = fmaf(w3, t0.x, acc0.x); acc0.y = fmaf(w3, t0.y, acc0.y);
        acc0.z = fmaf(w3, t0.z, acc0.z); acc0.w = fmaf(w3, t0.w, acc0.w);
        acc1.x = fmaf(w3, t1.x, acc1.x); acc1.y = fmaf(w3, t1.y, acc1.y);
        acc1.z = fmaf(w3, t1.z, acc1.z); acc1.w = fmaf(w3, t1.w, acc1.w);
    }
    for (; p < end; p++) {
        fma_row(acc0, acc1, g_w[p], (const float4*)(g_y + (size_t)g_col[p] * FD), lane);
    }

    float4* o = (float4*)(out + (size_t)gwarp * FD);
    o[lane * 2]     = acc0;
    o[lane * 2 + 1] = acc1;
}

// ---------------- launch (GEMM forked onto a side stream) ----------------
extern "C" void kernel_launch(void* const* d_in, const int* in_sizes, int n_in,
                              void* d_out, int out_size) {
    const float* x  = (const float*)d_in[0];
    const void*  ei = d_in[1];                 // int32 or int64, detected on device
    const float* C  = (const float*)d_in[2];
    const float* W  = (const float*)d_in[3];
    const float* b  = (const float*)d_in[4];
    float* out = (float*)d_out;

    cudaStream_t s2;
    cudaStreamCreateWithFlags(&s2, cudaStreamNonBlocking);
    cudaEvent_t eFork, eJoin;
    cudaEventCreateWithFlags(&eFork, cudaEventDisableTiming);
    cudaEventCreateWithFlags(&eJoin, cudaEventDisableTiming);

    // fork: GEMM (depends only on x, W) runs concurrently with CSR build
    cudaEventRecord(eFork, 0);
    cudaStreamWaitEvent(s2, eFork, 0);
    dim3 gg((NNP + GM_BM - 1) / GM_BM, FD / GM_BN);
    k_gemm_tc<<<gg, 256, 0, s2>>>(x, W);
    cudaEventRecord(eJoin, s2);

    // CSR build pipeline on the default stream
    k_init<<<(NN + 255) / 256, 256>>>((const int*)ei);
    k_deg<<<(NE + 255) / 256, 256>>>(ei, C);
    k_scan1<<<NB, 256>>>();
    k_scan2<<<1, 256>>>();
    k_scan3<<<NB, 256>>>();
    k_scatter<<<(NE + 255) / 256, 256>>>(ei, C);

    // join: SpMM needs both g_y and the CSR
    cudaStreamWaitEvent(0, eJoin, 0);
    k_spmm<<<(NN * 32 + 255) / 256, 256>>>(b, out);
}

// round 5
// speedup vs baseline: 1.7099x; 1.0662x over previous
#include <cuda_runtime.h>
#include <cuda_bf16.h>
#include <mma.h>

using namespace nvcuda;

#define NN 50000
#define NNP 50048              // 391 * 128, padded for unguarded wmma stores
#define NE 800000
#define FD 256
#define NB 196                 // (NN + 255) / 256 scan blocks

// ---------------- device scratch (no allocations allowed) ----------------
__device__ float g_dis[NN];        // degree, then deg^-1/2 in place
__device__ int   g_cnt[NN];        // edge count per row
__device__ int   g_off[NN];        // CSR row offsets (exclusive scan of cnt)
__device__ int   g_cur[NN];        // scatter cursors
__device__ int   g_col[NE];        // CSR col indices
__device__ float g_w[NE];          // CSR normalized weights
__device__ float g_y[(size_t)NNP * FD]; // y = x @ W^T (padded rows)
__device__ int   g_blk[NB];        // per-block count sums
__device__ int   g_blkoff[NB];     // exclusive scan of block sums
__device__ int   g_is64;           // edge_index dtype flag

__device__ __forceinline__ int edge_at(const void* ei, long long idx) {
    if (g_is64) return (int)((const long long*)ei)[idx];
    return ((const int*)ei)[idx];
}

// ---------------- init + dtype detect (block 0) ----------------
__global__ void k_init(const int* __restrict__ ei32) {
    int i = blockIdx.x * blockDim.x + threadIdx.x;
    if (i < NN) { g_dis[i] = 0.0f; g_cnt[i] = 0; }
    if (blockIdx.x == 0) {
        // int64 indices < 50000 => every odd 32-bit word is zero
        int nz = 0;
        if (threadIdx.x < 128) nz = (ei32[2 * threadIdx.x + 1] != 0) ? 1 : 0;
        int any = __syncthreads_or(nz);
        if (threadIdx.x == 0) g_is64 = (any == 0) ? 1 : 0;
    }
}

// ---------------- degree accumulation ----------------
__global__ void k_deg(const void* __restrict__ ei, const float* __restrict__ C) {
    int e = blockIdx.x * blockDim.x + threadIdx.x;
    if (e < NE) {
        int r = edge_at(ei, e);
        atomicAdd(&g_dis[r], C[e]);
        atomicAdd(&g_cnt[r], 1);
    }
}

// ---------------- hierarchical scan, stage 1: rsqrt + per-block sums ----
__global__ __launch_bounds__(256) void k_scan1() {
    __shared__ int s[256];
    int t = threadIdx.x;
    int i = blockIdx.x * 256 + t;
    int v = 0;
    if (i < NN) {
        float d = g_dis[i];
        g_dis[i] = (d > 0.0f) ? rsqrtf(d) : 0.0f;
        v = g_cnt[i];
    }
    s[t] = v;
    __syncthreads();
#pragma unroll
    for (int off = 128; off > 0; off >>= 1) {
        if (t < off) s[t] += s[t + off];
        __syncthreads();
    }
    if (t == 0) g_blk[blockIdx.x] = s[0];
}

// ---------------- stage 2: exclusive scan of NB block sums (1 block) -----
__global__ __launch_bounds__(256) void k_scan2() {
    __shared__ int s[256];
    int t = threadIdx.x;
    int v = (t < NB) ? g_blk[t] : 0;
    s[t] = v;
    __syncthreads();
#pragma unroll
    for (int off = 1; off < 256; off <<= 1) {
        int u = (t >= off) ? s[t - off] : 0;
        __syncthreads();
        s[t] += u;
        __syncthreads();
    }
    if (t < NB) g_blkoff[t] = s[t] - v;   // exclusive
}

// ---------------- stage 3: per-block exclusive scan + global offset ------
__global__ __launch_bounds__(256) void k_scan3() {
    __shared__ int s[256];
    int t = threadIdx.x;
    int i = blockIdx.x * 256 + t;
    int v = (i < NN) ? g_cnt[i] : 0;
    s[t] = v;
    __syncthreads();
#pragma unroll
    for (int off = 1; off < 256; off <<= 1) {
        int u = (t >= off) ? s[t - off] : 0;
        __syncthreads();
        s[t] += u;
        __syncthreads();
    }
    if (i < NN) {
        int excl = g_blkoff[blockIdx.x] + s[t] - v;
        g_off[i] = excl;
        g_cur[i] = excl;
    }
}

// ---------------- scatter edges into CSR + compute normalized weights ----
__global__ void k_scatter(const void* __restrict__ ei, const float* __restrict__ C) {
    int e = blockIdx.x * blockDim.x + threadIdx.x;
    if (e < NE) {
        int r  = edge_at(ei, e);
        int cl = edge_at(ei, (long long)NE + e);
        float w = g_dis[r] * C[e] * g_dis[cl];
        int p = atomicAdd(&g_cur[r], 1);
        g_col[p] = cl;
        g_w[p]   = w;
    }
}

// ---------------- tf32 tensor-core GEMM (one 128-col feature half) ------
// y[:, n0:n0+128] = x @ W[n0:n0+128, :]^T
// Block tile 128x128, 8 warps (2x4), warp tile 64x32 (4x2 wmma m16n16k8).
// BK=16 double-buffered. tf32 rounding applied ONCE at smem store.
#define GM_BM 128
#define GM_BN 128
#define GM_BK 16
#define BKP   20   // padded ld (floats)

__device__ __forceinline__ float4 cvt4(float4 v) {
    v.x = wmma::__float_to_tf32(v.x);
    v.y = wmma::__float_to_tf32(v.y);
    v.z = wmma::__float_to_tf32(v.z);
    v.w = wmma::__float_to_tf32(v.w);
    return v;
}

__global__ __launch_bounds__(256) void k_gemm_tc(const float* __restrict__ A,
                                                 const float* __restrict__ B,
                                                 int n0) {
    __shared__ __align__(16) float As[2][GM_BM][BKP];
    __shared__ __align__(16) float Bs[2][GM_BN][BKP];

    const int tid = threadIdx.x;
    const int w  = tid >> 5;
    const int wm = w >> 2;     // 0..1 -> 64-row slab
    const int wn = w & 3;      // 0..3 -> 32-col slab
    const int bm = blockIdx.x;

    wmma::fragment<wmma::accumulator, 16, 16, 8, float> acc[4][2];
#pragma unroll
    for (int i = 0; i < 4; i++)
#pragma unroll
        for (int j = 0; j < 2; j++) wmma::fill_fragment(acc[i][j], 0.0f);

    int aR[2], aC[2];
#pragma unroll
    for (int i = 0; i < 2; i++) {
        int f = tid + 256 * i;
        aR[i] = f >> 2;          // 0..127
        aC[i] = (f & 3) * 4;     // 0,4,8,12
    }
    int gAr[2]; bool av[2]; int gBr[2];
#pragma unroll
    for (int i = 0; i < 2; i++) {
        gAr[i] = bm * GM_BM + aR[i];
        av[i]  = (gAr[i] < NN);
        gBr[i] = n0 + aR[i];
    }

    const float4 z4 = make_float4(0.f, 0.f, 0.f, 0.f);
    float4 ra[2], rb[2];

#pragma unroll
    for (int i = 0; i < 2; i++) {
        ra[i] = av[i] ? *(const float4*)(A + (size_t)gAr[i] * FD + aC[i]) : z4;
        rb[i] = *(const float4*)(B + (size_t)gBr[i] * FD + aC[i]);
    }
#pragma unroll
    for (int i = 0; i < 2; i++) {
        *(float4*)&As[0][aR[i]][aC[i]] = cvt4(ra[i]);
        *(float4*)&Bs[0][aR[i]][aC[i]] = cvt4(rb[i]);
    }
    __syncthreads();

    const int NCH = FD / GM_BK; // 16
    for (int c = 0; c < NCH; c++) {
        const int p = c & 1, q = p ^ 1;
        if (c < NCH - 1) {
            const int k0 = (c + 1) * GM_BK;
#pragma unroll
            for (int i = 0; i < 2; i++) {
                ra[i] = av[i] ? *(const float4*)(A + (size_t)gAr[i] * FD + k0 + aC[i]) : z4;
                rb[i] = *(const float4*)(B + (size_t)gBr[i] * FD + k0 + aC[i]);
            }
        }

#pragma unroll
        for (int ks = 0; ks < 2; ks++) {
            const int k0 = ks * 8;
            wmma::fragment<wmma::matrix_a, 16, 16, 8, wmma::precision::tf32, wmma::row_major> af[4];
            wmma::fragment<wmma::matrix_b, 16, 16, 8, wmma::precision::tf32, wmma::col_major> bf[2];
#pragma unroll
            for (int i = 0; i < 4; i++)
                wmma::load_matrix_sync(af[i], &As[p][wm * 64 + i * 16][k0], BKP);
#pragma unroll
            for (int j = 0; j < 2; j++)
                wmma::load_matrix_sync(bf[j], &Bs[p][wn * 32 + j * 16][k0], BKP);
#pragma unroll
            for (int i = 0; i < 4; i++)
#pragma unroll
                for (int j = 0; j < 2; j++)
                    wmma::mma_sync(acc[i][j], af[i], bf[j], acc[i][j]);
        }

        if (c < NCH - 1) {
#pragma unroll
            for (int i = 0; i < 2; i++) {
                *(float4*)&As[q][aR[i]][aC[i]] = cvt4(ra[i]);
                *(float4*)&Bs[q][aR[i]][aC[i]] = cvt4(rb[i]);
            }
            __syncthreads();
        }
    }

    // epilogue: unguarded stores into padded g_y (NNP rows)
#pragma unroll
    for (int i = 0; i < 4; i++) {
        int gr = bm * GM_BM + wm * 64 + i * 16;
#pragma unroll
        for (int j = 0; j < 2; j++) {
            int gc = n0 + wn * 32 + j * 16;
            wmma::store_matrix_sync(g_y + (size_t)gr * FD + gc, acc[i][j], FD,
                                    wmma::mem_row_major);
        }
    }
}

// ---------------- SpMM (one 128-col feature half): warp per row ----------
// out[i, n0+lane*4 .. +3] = b[..] + sum_e w[e] * y[col[e], ..]
__global__ __launch_bounds__(256) void k_spmm(const float* __restrict__ bias,
                                              float* __restrict__ out,
                                              int n0) {
    int gwarp = (blockIdx.x * blockDim.x + threadIdx.x) >> 5;
    int lane  = threadIdx.x & 31;
    if (gwarp >= NN) return;

    const int beg = g_off[gwarp];
    const int end = beg + g_cnt[gwarp];
    const int fc  = n0 + lane * 4;   // this lane's float4 column

    float4 acc = *(const float4*)(bias + fc);

    int p = beg;
    for (; p + 3 < end; p += 4) {
        int   c0 = g_col[p],     c1 = g_col[p + 1];
        int   c2 = g_col[p + 2], c3 = g_col[p + 3];
        float w0 = g_w[p],       w1 = g_w[p + 1];
        float w2 = g_w[p + 2],   w3 = g_w[p + 3];
        float4 u = *(const float4*)(g_y + (size_t)c0 * FD + fc);
        float4 v = *(const float4*)(g_y + (size_t)c1 * FD + fc);
        float4 s = *(const float4*)(g_y + (size_t)c2 * FD + fc);
        float4 t = *(const float4*)(g_y + (size_t)c3 * FD + fc);
        acc.x = fmaf(w0, u.x, acc.x); acc.y = fmaf(w0, u.y, acc.y);
        acc.z = fmaf(w0, u.z, acc.z); acc.w = fmaf(w0, u.w, acc.w);
        acc.x = fmaf(w1, v.x, acc.x); acc.y = fmaf(w1, v.y, acc.y);
        acc.z = fmaf(w1, v.z, acc.z); acc.w = fmaf(w1, v.w, acc.w);
        acc.x = fmaf(w2, s.x, acc.x); acc.y = fmaf(w2, s.y, acc.y);
        acc.z = fmaf(w2, s.z, acc.z); acc.w = fmaf(w2, s.w, acc.w);
        acc.x = fmaf(w3, t.x, acc.x); acc.y = fmaf(w3, t.y, acc.y);
        acc.z = fmaf(w3, t.z, acc.z); acc.w = fmaf(w3, t.w, acc.w);
    }
    for (; p < end; p++) {
        float wv = g_w[p];
        float4 u = *(const float4*)(g_y + (size_t)g_col[p] * FD + fc);
        acc.x = fmaf(wv, u.x, acc.x); acc.y = fmaf(wv, u.y, acc.y);
        acc.z = fmaf(wv, u.z, acc.z); acc.w = fmaf(wv, u.w, acc.w);
    }

    *(float4*)(out + (size_t)gwarp * FD + fc) = acc;
}

// ---------------- launch: two-half GEMM/SpMM pipeline --------------------
extern "C" void kernel_launch(void* const* d_in, const int* in_sizes, int n_in,
                              void* d_out, int out_size) {
    const float* x  = (const float*)d_in[0];
    const void*  ei = d_in[1];                 // int32 or int64, detected on device
    const float* C  = (const float*)d_in[2];
    const float* W  = (const float*)d_in[3];
    const float* b  = (const float*)d_in[4];
    float* out = (float*)d_out;

    cudaStream_t s2;
    cudaStreamCreateWithFlags(&s2, cudaStreamNonBlocking);
    cudaEvent_t eFork, e0, e1;
    cudaEventCreateWithFlags(&eFork, cudaEventDisableTiming);
    cudaEventCreateWithFlags(&e0, cudaEventDisableTiming);
    cudaEventCreateWithFlags(&e1, cudaEventDisableTiming);

    // fork: GEMM halves (depend only on x, W) run on side stream
    cudaEventRecord(eFork, 0);
    cudaStreamWaitEvent(s2, eFork, 0);
    dim3 gg(NNP / GM_BM, 1);
    k_gemm_tc<<<gg, 256, 0, s2>>>(x, W, 0);
    cudaEventRecord(e0, s2);
    k_gemm_tc<<<gg, 256, 0, s2>>>(x, W, 128);
    cudaEventRecord(e1, s2);

    // CSR build pipeline on the default stream (hidden under GEMM_h0)
    k_init<<<(NN + 255) / 256, 256>>>((const int*)ei);
    k_deg<<<(NE + 255) / 256, 256>>>(ei, C);
    k_scan1<<<NB, 256>>>();
    k_scan2<<<1, 256>>>();
    k_scan3<<<NB, 256>>>();
    k_scatter<<<(NE + 255) / 256, 256>>>(ei, C);

    // SpMM_h0 overlaps GEMM_h1; SpMM_h1 after GEMM_h1
    cudaStreamWaitEvent(0, e0, 0);
    k_spmm<<<(NN * 32 + 255) / 256, 256>>>(b, out, 0);
    cudaStreamWaitEvent(0, e1, 0);
    k_spmm<<<(NN * 32 + 255) / 256, 256>>>(b, out, 128);
}